// round 11
// baseline (speedup 1.0000x reference)
#include <cuda_runtime.h>
#include <cuda_fp16.h>
#include <math.h>
#include <stdint.h>
#include <cstdint>

// Problem constants
#define BB 4
#define NN 2048
#define DD 1024
#define ROWS 8192      // B*N
#define NF 37

// ---------------- device scratch (allocation-free) ----------------
__device__ float g_senses[8192 * 3072];
__device__ float g_partial[4 * 16 * 1024];
__device__ float g_xmean [4 * 1024];
__device__ float g_ctx   [4 * 1024];
__device__ float g_selctx[4 * 3];
__device__ float g_selw  [8192 * 3];
__device__ float g_rowf  [8192 * 8];
__device__ float g_compat[1024];
__device__ float g_Wfeat [1024 * NF];
__device__ float g_bfeat [NF];
__device__ float g_Wcomb [1024 * 128];   // cols 0..110 = Wsense@Wfeat, 111..113 = W_sel[:D], 114..127 zero
__device__ float g_bcomb [3 * NF];
__device__ float g_xC    [2 * 8192 * 128];

// fp16 planes
__device__ __half g_xA   [8192 * 1024];       // hi only
__device__ __half g_WsT  [3072 * 1024];       // hi only
__device__ __half g_xnA  [8192 * 1024];       // hi only
__device__ __half g_WvT  [1024 * 1024];       // hi only
__device__ __half g_VT   [2 * 4 * 1024 * 2048];  // hi+lo (refines V in attn@V)
__device__ __half g_attnA[8192 * 2048];
__device__ __half g_aoA  [8192 * 1024];       // hi only
__device__ __half g_WoT  [1024 * 1024];       // hi only

__device__ __forceinline__ float sp_(float z) {
    return z > 20.f ? z : log1pf(expf(z));
}
__device__ __forceinline__ float neg_inf_() { return __int_as_float(0xff800000u); }

__device__ __forceinline__ uint32_t smem_u32(const void* p) {
    uint32_t a;
    asm("{ .reg .u64 t; cvta.to.shared.u64 t, %1; cvt.u32.u64 %0, t; }" : "=r"(a) : "l"(p));
    return a;
}
__device__ __forceinline__ void ldm_x4(uint32_t* r, uint32_t addr) {
    asm volatile("ldmatrix.sync.aligned.m8n8.x4.shared.b16 {%0,%1,%2,%3}, [%4];"
        : "=r"(r[0]), "=r"(r[1]), "=r"(r[2]), "=r"(r[3]) : "r"(addr));
}
__device__ __forceinline__ void mma_f16(float* c, const uint32_t* a, const uint32_t* b) {
    asm volatile("mma.sync.aligned.m16n8k16.row.col.f32.f16.f16.f32 "
        "{%0,%1,%2,%3}, {%4,%5,%6,%7}, {%8,%9}, {%0,%1,%2,%3};"
        : "+f"(c[0]), "+f"(c[1]), "+f"(c[2]), "+f"(c[3])
        : "r"(a[0]), "r"(a[1]), "r"(a[2]), "r"(a[3]), "r"(b[0]), "r"(b[1]));
}
__device__ __forceinline__ void cp_async16(uint32_t s, const void* g) {
    asm volatile("cp.async.cg.shared.global [%0], [%1], 16;" :: "r"(s), "l"(g));
}
__device__ __forceinline__ void cp_commit() { asm volatile("cp.async.commit_group;" ::: "memory"); }
template<int N> __device__ __forceinline__ void cp_wait() {
    asm volatile("cp.async.wait_group %0;" :: "n"(N) : "memory");
}

// ---------------- fp16 split GEMM (mma.sync, 3-stage cp.async pipeline) ------
// C = A@B (+bias). A: SAP fp16 planes [M][K]; B: SBP planes [N][K] (pre-transposed).
// Terms (ci,cj) with ci+cj < max(SAP,SBP) accumulate in fp32.
// OUTM: 0 = fp32 row-major; 1 = fp16 hi plane (+lo plane iff psC!=0);
//       2 = fp16 hi/lo planes written TRANSPOSED batch-split (VT layout).
template<int SAP, int SBP, bool CAUSAL, int OUTM>
__global__ __launch_bounds__(256, 2)
void hgemm(const __half* __restrict__ A, const __half* __restrict__ B,
           void* __restrict__ Cv, const float* __restrict__ bias,
           int K, int lda, int ldb, int ldc,
           size_t psA, size_t psB, size_t psC,
           size_t sA, size_t sB, size_t sC) {
    extern __shared__ char smx[];
    A += (size_t)blockIdx.z * sA;
    B += (size_t)blockIdx.z * sB;
    const int by = CAUSAL ? (gridDim.y - 1 - blockIdx.y) : blockIdx.y;
    const int rowStart = by * 128;
    const int colStart = blockIdx.x * 128;
    const int kmax = CAUSAL ? min(K, rowStart + 128) : K;
    const int tid = threadIdx.x, lane = tid & 31, wid = tid >> 5;
    const int mW = (wid >> 2) * 64, nW = (wid & 3) * 32;
    const uint32_t smBase = smem_u32(smx);
    constexpr uint32_t PL  = 8192u;
    constexpr uint32_t STG = (uint32_t)(SAP + SBP) * PL;
    constexpr int MAXS = (SAP > SBP) ? SAP : SBP;

    float acc[4][4][4];
    #pragma unroll
    for (int i = 0; i < 4; ++i)
        #pragma unroll
        for (int j = 0; j < 4; ++j)
            #pragma unroll
            for (int e = 0; e < 4; ++e) acc[i][j][e] = 0.f;

    const int rA = mW + (lane & 15);
    const int rB = nW + ((lane >> 4) << 3) + (lane & 7);
    const uint32_t swA = (uint32_t)((rA >> 1) & 3);
    const uint32_t swB = (uint32_t)((rB >> 1) & 3);
    const uint32_t cA = (uint32_t)(lane >> 4);
    const uint32_t cB = (uint32_t)((lane >> 3) & 1);
    uint32_t aRow[4], bRow[2];
    #pragma unroll
    for (int am = 0; am < 4; ++am) aRow[am] = (uint32_t)(rA + am * 16) * 64u;
    #pragma unroll
    for (int np = 0; np < 2; ++np) bRow[np] = (uint32_t)(rB + np * 16) * 64u;

    const int r2 = tid >> 2, c2 = tid & 3;

    auto loadStage = [&](int st, int k0) {
        uint32_t sb = smBase + (uint32_t)st * STG;
        #pragma unroll
        for (int p = 0; p < SAP; ++p) {
            const __half* gp = A + (size_t)p * psA + (size_t)rowStart * lda + k0;
            #pragma unroll
            for (int l = 0; l < 2; ++l) {
                int r = l * 64 + r2;
                uint32_t sa = sb + (uint32_t)p * PL + (uint32_t)r * 64u +
                              ((((uint32_t)c2) ^ (((uint32_t)r >> 1) & 3u)) << 4);
                cp_async16(sa, gp + (size_t)r * lda + c2 * 8);
            }
        }
        #pragma unroll
        for (int p = 0; p < SBP; ++p) {
            const __half* gp = B + (size_t)p * psB + (size_t)colStart * ldb + k0;
            #pragma unroll
            for (int l = 0; l < 2; ++l) {
                int r = l * 64 + r2;
                uint32_t sa = sb + (uint32_t)(SAP + p) * PL + (uint32_t)r * 64u +
                              ((((uint32_t)c2) ^ (((uint32_t)r >> 1) & 3u)) << 4);
                cp_async16(sa, gp + (size_t)r * ldb + c2 * 8);
            }
        }
    };

    const int nIter = kmax >> 5;
    if (0 < nIter) loadStage(0, 0);
    cp_commit();
    if (1 < nIter) loadStage(1, 32);
    cp_commit();

    for (int it = 0; it < nIter; ++it) {
        if (it + 1 < nIter) cp_wait<1>(); else cp_wait<0>();
        __syncthreads();
        int nl = it + 2;
        if (nl < nIter) loadStage(nl - (nl / 3) * 3, nl << 5);
        cp_commit();

        uint32_t sb = smBase + (uint32_t)(it - (it / 3) * 3) * STG;
        #pragma unroll
        for (int ks = 0; ks < 2; ++ks) {
            uint32_t af[SAP][4][4], bf[SBP][2][4];
            #pragma unroll
            for (int p = 0; p < SAP; ++p)
                #pragma unroll
                for (int am = 0; am < 4; ++am)
                    ldm_x4(af[p][am], sb + (uint32_t)p * PL + aRow[am] +
                           ((((uint32_t)(2 * ks) + cA) ^ swA) << 4));
            #pragma unroll
            for (int p = 0; p < SBP; ++p)
                #pragma unroll
                for (int np = 0; np < 2; ++np)
                    ldm_x4(bf[p][np], sb + (uint32_t)(SAP + p) * PL + bRow[np] +
                           ((((uint32_t)(2 * ks) + cB) ^ swB) << 4));
            #pragma unroll
            for (int ci = 0; ci < SAP; ++ci)
                #pragma unroll
                for (int cj = 0; cj < SBP; ++cj) {
                    if (ci + cj >= MAXS) continue;
                    #pragma unroll
                    for (int am = 0; am < 4; ++am)
                        #pragma unroll
                        for (int an = 0; an < 4; ++an)
                            mma_f16(acc[am][an], af[ci][am], &bf[cj][an >> 1][(an & 1) * 2]);
                }
        }
    }

    #pragma unroll
    for (int am = 0; am < 4; ++am) {
        int row = rowStart + mW + am * 16 + (lane >> 2);
        #pragma unroll
        for (int an = 0; an < 4; ++an) {
            int col = colStart + nW + an * 8 + (lane & 3) * 2;
            float b0 = bias ? bias[col] : 0.f, b1 = bias ? bias[col + 1] : 0.f;
            float v0 = acc[am][an][0] + b0, v1 = acc[am][an][1] + b1;
            float v2 = acc[am][an][2] + b0, v3 = acc[am][an][3] + b1;
            if (OUTM == 0) {
                float* C = (float*)Cv + (size_t)blockIdx.z * sC;
                *(float2*)(C + (size_t)row * ldc + col) = make_float2(v0, v1);
                *(float2*)(C + (size_t)(row + 8) * ldc + col) = make_float2(v2, v3);
            } else if (OUTM == 1) {
                __half* Cp = (__half*)Cv + (size_t)blockIdx.z * sC;
                __half h0 = __float2half(v0), h1 = __float2half(v1);
                __half h2 = __float2half(v2), h3 = __float2half(v3);
                __half2 hh01; hh01.x = h0; hh01.y = h1;
                __half2 hh23; hh23.x = h2; hh23.y = h3;
                *(__half2*)(Cp + (size_t)row * ldc + col) = hh01;
                *(__half2*)(Cp + (size_t)(row + 8) * ldc + col) = hh23;
                if (psC) {
                    __half2 ll01; ll01.x = __float2half(v0 - __half2float(h0));
                                  ll01.y = __float2half(v1 - __half2float(h1));
                    __half2 ll23; ll23.x = __float2half(v2 - __half2float(h2));
                                  ll23.y = __float2half(v3 - __half2float(h3));
                    *(__half2*)(Cp + psC + (size_t)row * ldc + col) = ll01;
                    *(__half2*)(Cp + psC + (size_t)(row + 8) * ldc + col) = ll23;
                }
            } else {
                // OUTM == 2: transposed batch-split VT write: VT[b][col][row&2047]
                __half* Cp = (__half*)Cv;
                size_t a0 = ((size_t)(row >> 11) << 21) + (size_t)col * 2048 + (row & 2047);
                __half h0 = __float2half(v0), h1 = __float2half(v1);
                __half h2 = __float2half(v2), h3 = __float2half(v3);
                Cp[a0]            = h0;
                Cp[a0 + 2048]     = h1;
                Cp[a0 + 8]        = h2;
                Cp[a0 + 2056]     = h3;
                Cp[psC + a0]        = __float2half(v0 - __half2float(h0));
                Cp[psC + a0 + 2048] = __float2half(v1 - __half2float(h1));
                Cp[psC + a0 + 8]    = __float2half(v2 - __half2float(h2));
                Cp[psC + a0 + 2056] = __float2half(v3 - __half2float(h3));
            }
        }
    }
}

// ---------------- conversion kernels ----------------

// fp32 -> fp16 (hi plane only)
__global__ void k_cvtA(const float* __restrict__ src, __half* __restrict__ dst) {
    size_t i = ((size_t)blockIdx.x * 256 + threadIdx.x) * 4;
    float4 v = *(const float4*)(src + i);
    __half2 a; a.x = __float2half(v.x); a.y = __float2half(v.y);
    __half2 b; b.x = __float2half(v.z); b.y = __float2half(v.w);
    *(__half2*)(dst + i) = a; *(__half2*)(dst + i + 2) = b;
}

// transpose: dst[n][k] = fp16(src[k][n]) (hi only)
__global__ void k_convBt(const float* __restrict__ src, __half* __restrict__ dst,
                         int lds, int ldd) {
    int n0 = blockIdx.x * 32, k0 = blockIdx.y * 32;
    __shared__ float t[32][33];
    int tx = threadIdx.x & 31, ty = threadIdx.x >> 5;
    #pragma unroll
    for (int l = 0; l < 4; ++l)
        t[ty + l * 8][tx] = src[(size_t)(k0 + ty + l * 8) * lds + n0 + tx];
    __syncthreads();
    #pragma unroll
    for (int l = 0; l < 4; ++l) {
        int n = ty + l * 8;
        dst[(size_t)(n0 + n) * ldd + k0 + tx] = __float2half(t[tx][n]);
    }
}

// ---------------- merged prep kernels ----------------

// blocks [0,256): meanpart | 256: compat | [257,405): packfeat | [405,417): packsel
__global__ void k_prep1(const float* __restrict__ x, const float* __restrict__ L,
                        const float* __restrict__ W_charge, const float* __restrict__ b_charge,
                        const float* __restrict__ W_shell,  const float* __restrict__ b_shell,
                        const float* __restrict__ W_class,  const float* __restrict__ b_class,
                        const float* __restrict__ W_mass,   const float* __restrict__ b_mass,
                        const float* __restrict__ W_sel) {
    int blk = blockIdx.x, tid = threadIdx.x;
    if (blk < 256) {
        int d  = (blk & 3) * 256 + tid;
        int bc = blk >> 2;
        int b  = bc >> 4, c = bc & 15;
        const float* xp = x + ((size_t)b * NN + c * 128) * DD + d;
        float s = 0.f;
        #pragma unroll 8
        for (int n = 0; n < 128; n++) s += xp[(size_t)n * DD];
        g_partial[bc * 1024 + d] = s;
    } else if (blk == 256) {
        for (int t = tid; t < 1024; t += 256) {
            int i = t >> 5, j = t & 31;
            float v = (L[i * 32 + j] + L[j * 32 + i]) * 0.5f;
            g_compat[t] = 1.f / (1.f + expf(-v));
        }
    } else if (blk < 405) {
        int idx = (blk - 257) * 256 + tid;
        if (idx < 1024 * NF) {
            int k = idx / NF, c = idx % NF;
            float v;
            if (c == 0)       v = W_charge[k];
            else if (c <= 3)  v = W_shell[k * 3 + (c - 1)];
            else if (c <= 35) v = W_class[k * 32 + (c - 4)];
            else              v = W_mass[k];
            g_Wfeat[k * NF + c] = v;
        }
        if (idx < NF) {
            float v;
            if (idx == 0)       v = b_charge[0];
            else if (idx <= 3)  v = b_shell[idx - 1];
            else if (idx <= 35) v = b_class[idx - 4];
            else                v = b_mass[0];
            g_bfeat[idx] = v;
        }
    } else {
        int idx = (blk - 405) * 256 + tid;    // 0..3071
        if (idx < 3072) {
            int k = idx / 3, s = idx % 3;
            g_Wcomb[k * 128 + 111 + s] = W_sel[(size_t)k * 3 + s];
        }
    }
}

// blocks [0,16): meanfin | 16: bcomb
__global__ void k_prep2(const float* __restrict__ b_sense) {
    int blk = blockIdx.x, tid = threadIdx.x;
    if (blk < 16) {
        int idx = blk * 256 + tid;
        int b = idx >> 10, d = idx & 1023;
        float s = 0.f;
        #pragma unroll
        for (int c = 0; c < 16; c++) s += g_partial[(b * 16 + c) * 1024 + d];
        g_xmean[idx] = s * (1.f / (float)NN);
    } else {
        int c = tid;
        if (c < 3 * NF) {
            int s = c / NF, cc = c % NF;
            float acc = 0.f;
            for (int k = 0; k < 1024; k++)
                acc += b_sense[s * 1024 + k] * g_Wfeat[k * NF + cc];
            g_bcomb[c] = acc;
        }
    }
}

__global__ void k_ctxpart(const float* __restrict__ W_ctx) {
    int d = blockIdx.x * 256 + threadIdx.x;
    int b = blockIdx.y;
    int z = blockIdx.z;
    const float* xm = g_xmean + b * 1024 + z * 128;
    const float* W  = W_ctx + (size_t)(z * 128) * 1024 + d;
    float acc = 0.f;
    #pragma unroll 8
    for (int k = 0; k < 128; k++) acc += xm[k] * W[(size_t)k * 1024];
    g_partial[(z * 4 + b) * 1024 + d] = acc;
}

__global__ void k_ctxfin(const float* __restrict__ b_ctx) {
    int idx = blockIdx.x * 256 + threadIdx.x;
    int b = idx >> 10, d = idx & 1023;
    float s = 0.f;
    #pragma unroll
    for (int z = 0; z < 8; z++) s += g_partial[(z * 4 + b) * 1024 + d];
    g_ctx[idx] = s + b_ctx[d];
}

__global__ void k_selctx(const float* __restrict__ W_sel, const float* __restrict__ b_sel) {
    int s = blockIdx.x, b = blockIdx.y;
    int tid = threadIdx.x;
    const float* c = g_ctx + b * 1024;
    float p = 0.f;
    for (int k = tid; k < 1024; k += 128) p += c[k] * W_sel[(size_t)(1024 + k) * 3 + s];
    __shared__ float red[128];
    red[tid] = p; __syncthreads();
    for (int o = 64; o; o >>= 1) { if (tid < o) red[tid] += red[tid + o]; __syncthreads(); }
    if (tid == 0) g_selctx[b * 3 + s] = red[0] + b_sel[s];
}

// per-row: sel softmax (from xC cols 111..113) -> g_selw, then features -> g_rowf
__global__ void k_rowprep() {
    int row = blockIdx.x;
    int b   = row >> 11;
    int tid = threadIdx.x;   // 64
    __shared__ float fv[NF];
    __shared__ float sw[3];
    const float* xc0 = g_xC + (size_t)row * 128;
    const float* xc1 = g_xC + (size_t)8192 * 128 + (size_t)row * 128;
    if (tid < 3)
        fv[tid] = xc0[111 + tid] + xc1[111 + tid] + g_selctx[b * 3 + tid];
    __syncthreads();
    if (tid == 0) {
        float l0 = fv[0], l1 = fv[1], l2 = fv[2];
        float m = fmaxf(l0, fmaxf(l1, l2));
        float e0 = expf(l0 - m), e1 = expf(l1 - m), e2 = expf(l2 - m);
        float inv = 1.f / (e0 + e1 + e2);
        sw[0] = e0 * inv; sw[1] = e1 * inv; sw[2] = e2 * inv;
        g_selw[row * 3 + 0] = sw[0];
        g_selw[row * 3 + 1] = sw[1];
        g_selw[row * 3 + 2] = sw[2];
    }
    __syncthreads();
    if (tid < NF) {
        float v0 = xc0[tid]          + xc1[tid]          + g_bcomb[tid];
        float v1 = xc0[NF + tid]     + xc1[NF + tid]     + g_bcomb[NF + tid];
        float v2 = xc0[2 * NF + tid] + xc1[2 * NF + tid] + g_bcomb[2 * NF + tid];
        fv[tid] = g_bfeat[tid] + sw[0] * v0 + sw[1] * v1 + sw[2] * v2;
    }
    __syncthreads();
    if (tid == 0) {
        float* rf = g_rowf + (size_t)row * 8;
        rf[0] = tanhf(fv[0]);
        float s0 = fv[1], s1 = fv[2], s2 = fv[3];
        float m = fmaxf(s0, fmaxf(s1, s2));
        float e0 = expf(s0 - m), e1 = expf(s1 - m), e2 = expf(s2 - m);
        float inv = 1.f / (e0 + e1 + e2);
        rf[1] = e0 * inv; rf[2] = e1 * inv; rf[3] = e2 * inv;
        float best = fv[4]; int bi = 0;
        #pragma unroll
        for (int c = 1; c < 32; c++) { float v = fv[4 + c]; if (v > best) { best = v; bi = c; } }
        rf[4] = sp_(fv[36]) + 0.5f;
        rf[5] = __int_as_float(bi);
        rf[6] = 0.f; rf[7] = 0.f;
    }
}

// elementwise combine: xnew = sum_s w_s * senses_s -> fp16 hi plane
__global__ void k_combine2() {
    int row = blockIdx.x;
    int tid = threadIdx.x;   // 256
    float w0 = g_selw[row * 3 + 0];
    float w1 = g_selw[row * 3 + 1];
    float w2 = g_selw[row * 3 + 2];
    const float4* S0 = (const float4*)(g_senses + (size_t)row * 3072);
    const float4* S1 = (const float4*)(g_senses + (size_t)row * 3072 + 1024);
    const float4* S2 = (const float4*)(g_senses + (size_t)row * 3072 + 2048);
    float4 a = S0[tid], bb = S1[tid], c = S2[tid];
    float o0 = w0 * a.x + w1 * bb.x + w2 * c.x;
    float o1 = w0 * a.y + w1 * bb.y + w2 * c.y;
    float o2 = w0 * a.z + w1 * bb.z + w2 * c.z;
    float o3 = w0 * a.w + w1 * bb.w + w2 * c.w;
    size_t off = (size_t)row * 1024 + tid * 4;
    __half2 hh01; hh01.x = __float2half(o0); hh01.y = __float2half(o1);
    __half2 hh23; hh23.x = __float2half(o2); hh23.y = __float2half(o3);
    *(__half2*)(g_xnA + off) = hh01;
    *(__half2*)(g_xnA + off + 2) = hh23;
}

// energy scores + causal softmax (bounded loops) -> fp16 attn plane
__global__ void k_scores(const float* __restrict__ w_charge, const float* __restrict__ w_shell,
                         const float* __restrict__ w_distance, const float* __restrict__ w_mass,
                         const float* __restrict__ w_valence, const float* __restrict__ temperature) {
    int gi = blockIdx.x;
    int b  = gi >> 11;
    int i  = NN - 1 - (gi & 2047);
    int rowEnd = ((i >> 7) + 1) << 7;
    int tid = threadIdx.x;
    __shared__ float sc[2048];
    __shared__ float cp[1024];
    __shared__ float red[256];
    for (int t = tid; t < 1024; t += 256) cp[t] = g_compat[t];

    float spc = sp_(w_charge[0]);
    float sps = sp_(w_shell[0]);
    float spd = sp_(w_distance[0]);
    float spm = sp_(w_mass[0]);
    float spv = sp_(w_valence[0]);
    float invt = 1.f / sp_(temperature[0]);

    const float4* rf = (const float4*)g_rowf;
    int base = b * NN;
    float4 m0 = rf[(size_t)(base + i) * 2];
    float4 m1 = rf[(size_t)(base + i) * 2 + 1];
    float ci = m0.x, si0 = m0.y, si1 = m0.z, si2 = m0.w;
    float mi = m1.x;
    int cli = __float_as_int(m1.y) * 32;
    __syncthreads();

    for (int j = tid; j <= i; j += 256) {
        float4 f0 = rf[(size_t)(base + j) * 2];
        float4 f1 = rf[(size_t)(base + j) * 2 + 1];
        float d0 = fabsf(si0 - f0.y);
        float d1 = fabsf(si1 - f0.z);
        float d2 = fabsf(si2 - f0.w);
        float dist = (float)(i - j);
        float E = spc * ci * f0.x + sps * (d0 + d1 + d2)
                - spd * __fdividef(1.f, 1.f + 0.1f * dist)
                + spm * 0.1f * mi * f1.x - spv;
        sc[j] = -E * invt * cp[cli + __float_as_int(f1.y)];
    }
    __syncthreads();

    float lm = neg_inf_();
    for (int j = tid; j <= i; j += 256) lm = fmaxf(lm, sc[j]);
    red[tid] = lm; __syncthreads();
    for (int o = 128; o; o >>= 1) { if (tid < o) red[tid] = fmaxf(red[tid], red[tid + o]); __syncthreads(); }
    float mx = red[0]; __syncthreads();

    float ls = 0.f;
    for (int j = tid; j <= i; j += 256) { float e = expf(sc[j] - mx); sc[j] = e; ls += e; }
    red[tid] = ls; __syncthreads();
    for (int o = 128; o; o >>= 1) { if (tid < o) red[tid] += red[tid + o]; __syncthreads(); }
    float inv = 1.f / red[0];

    __half* ar = g_attnA + (size_t)(base + i) * NN;
    for (int j = tid; j < rowEnd; j += 256)
        ar[j] = __float2half(j <= i ? sc[j] * inv : 0.f);
}

// ---------------- fp32 tiled SGEMM (feat path, with batch strides) -----------
__global__ __launch_bounds__(256)
void sgemm128(const float* __restrict__ A, const float* __restrict__ B,
              float* __restrict__ C, const float* __restrict__ bias,
              int M, int N, int K, int lda, int ldb, int ldc,
              size_t sA, size_t sB, size_t sC) {
    A += (size_t)blockIdx.z * sA;
    B += (size_t)blockIdx.z * sB;
    C += (size_t)blockIdx.z * sC;
    int rowStart = blockIdx.y * 128;
    int colStart = blockIdx.x * 128;

    __shared__ float As[16][128];
    __shared__ float Bs[16][128];
    int tid = threadIdx.x;
    int tx = tid & 15, ty = tid >> 4;
    float acc[8][8];
    #pragma unroll
    for (int i = 0; i < 8; i++)
        #pragma unroll
        for (int j = 0; j < 8; j++) acc[i][j] = 0.f;

    const bool n_vec = ((N & 3) == 0);

    for (int k0 = 0; k0 < K; k0 += 16) {
        #pragma unroll
        for (int l = 0; l < 2; l++) {
            int idx = tid + l * 256;
            int m = idx >> 2;
            int kq = (idx & 3) * 4;
            float4 v = *reinterpret_cast<const float4*>(
                A + (size_t)(rowStart + m) * lda + k0 + kq);
            As[kq + 0][m] = v.x; As[kq + 1][m] = v.y; As[kq + 2][m] = v.z; As[kq + 3][m] = v.w;
        }
        #pragma unroll
        for (int l = 0; l < 2; l++) {
            int idx = tid + l * 256;
            int kr = idx >> 5;
            int nq = (idx & 31) * 4;
            int col = colStart + nq;
            float4 v;
            if (n_vec && col + 3 < N) {
                v = *reinterpret_cast<const float4*>(B + (size_t)(k0 + kr) * ldb + col);
            } else {
                const float* bp = B + (size_t)(k0 + kr) * ldb;
                v.x = (col + 0 < N) ? bp[col + 0] : 0.f;
                v.y = (col + 1 < N) ? bp[col + 1] : 0.f;
                v.z = (col + 2 < N) ? bp[col + 2] : 0.f;
                v.w = (col + 3 < N) ? bp[col + 3] : 0.f;
            }
            *reinterpret_cast<float4*>(&Bs[kr][nq]) = v;
        }
        __syncthreads();
        #pragma unroll
        for (int kk = 0; kk < 16; kk++) {
            float ra[8], rb[8];
            *(float4*)&ra[0] = *(float4*)&As[kk][ty * 8];
            *(float4*)&ra[4] = *(float4*)&As[kk][ty * 8 + 4];
            *(float4*)&rb[0] = *(float4*)&Bs[kk][tx * 8];
            *(float4*)&rb[4] = *(float4*)&Bs[kk][tx * 8 + 4];
            #pragma unroll
            for (int i = 0; i < 8; i++)
                #pragma unroll
                for (int j = 0; j < 8; j++)
                    acc[i][j] += ra[i] * rb[j];
        }
        __syncthreads();
    }

    #pragma unroll
    for (int i = 0; i < 8; i++) {
        size_t row = rowStart + ty * 8 + i;
        #pragma unroll
        for (int j = 0; j < 8; j++) {
            int col = colStart + tx * 8 + j;
            if (col < N) {
                float v = acc[i][j] + (bias ? bias[col] : 0.f);
                C[row * (size_t)ldc + col] = v;
            }
        }
    }
}

// ---------------- host ----------------
extern "C" void kernel_launch(void* const* d_in, const int* in_sizes, int n_in,
                              void* d_out, int out_size) {
    const float* x         = (const float*)d_in[0];
    const float* W_sense   = (const float*)d_in[1];
    const float* b_sense   = (const float*)d_in[2];
    const float* W_ctx     = (const float*)d_in[3];
    const float* b_ctx     = (const float*)d_in[4];
    const float* W_sel     = (const float*)d_in[5];
    const float* b_sel     = (const float*)d_in[6];
    const float* W_charge  = (const float*)d_in[7];
    const float* b_charge  = (const float*)d_in[8];
    const float* W_shell   = (const float*)d_in[9];
    const float* b_shell   = (const float*)d_in[10];
    const float* W_class   = (const float*)d_in[11];
    const float* b_class   = (const float*)d_in[12];
    const float* W_mass    = (const float*)d_in[13];
    const float* b_mass    = (const float*)d_in[14];
    const float* compatL   = (const float*)d_in[17];
    const float* w_charge  = (const float*)d_in[18];
    const float* w_shell   = (const float*)d_in[19];
    const float* w_distance= (const float*)d_in[20];
    const float* w_mass    = (const float*)d_in[21];
    const float* w_valence = (const float*)d_in[22];
    const float* temperature=(const float*)d_in[23];
    const float* W_v       = (const float*)d_in[24];
    const float* b_v       = (const float*)d_in[25];
    const float* W_out     = (const float*)d_in[26];
    const float* b_out     = (const float*)d_in[27];
    float* out = (float*)d_out;

    void *p_senses, *p_Wfeat, *p_Wcomb, *p_xC;
    void *p_xA, *p_WsT, *p_xnA, *p_WvT, *p_VT, *p_attnA, *p_aoA, *p_WoT;
    cudaGetSymbolAddress(&p_senses, g_senses);
    cudaGetSymbolAddress(&p_Wfeat,  g_Wfeat);
    cudaGetSymbolAddress(&p_Wcomb,  g_Wcomb);
    cudaGetSymbolAddress(&p_xC,     g_xC);
    cudaGetSymbolAddress(&p_xA,     g_xA);
    cudaGetSymbolAddress(&p_WsT,    g_WsT);
    cudaGetSymbolAddress(&p_xnA,    g_xnA);
    cudaGetSymbolAddress(&p_WvT,    g_WvT);
    cudaGetSymbolAddress(&p_VT,     g_VT);
    cudaGetSymbolAddress(&p_attnA,  g_attnA);
    cudaGetSymbolAddress(&p_aoA,    g_aoA);
    cudaGetSymbolAddress(&p_WoT,    g_WoT);

    const int SM11 = 3 * 2 * 8192;   // 49152
    const int SM12 = 3 * 3 * 8192;   // 73728
    cudaFuncSetAttribute(hgemm<1, 1, false, 0>, cudaFuncAttributeMaxDynamicSharedMemorySize, SM11);
    cudaFuncSetAttribute(hgemm<1, 1, false, 2>, cudaFuncAttributeMaxDynamicSharedMemorySize, SM11);
    cudaFuncSetAttribute(hgemm<1, 2, true, 1>,  cudaFuncAttributeMaxDynamicSharedMemorySize, SM12);

    const size_t PSVT = (size_t)4 * 1024 * 2048;

    // ---- prep (merged) ----
    k_prep1<<<417, 256>>>(x, compatL, W_charge, b_charge, W_shell, b_shell,
                          W_class, b_class, W_mass, b_mass, W_sel);
    k_prep2<<<17, 256>>>(b_sense);
    k_ctxpart<<<dim3(4, 4, 8), 256>>>(W_ctx);
    k_ctxfin<<<16, 256>>>(b_ctx);
    k_selctx<<<dim3(3, 4), 128>>>(W_sel, b_sel);
    // Wcomb cols 0..110
    sgemm128<<<dim3(1, 8, 3), 256>>>(W_sense, (const float*)p_Wfeat, (float*)p_Wcomb, nullptr,
                                     1024, NF, 1024, 3072, NF, 128,
                                     1024, 0, NF);
    // xC = x @ Wcomb (feat partials + sel logits), split-K 2
    sgemm128<<<dim3(1, 64, 2), 256>>>(x, (const float*)p_Wcomb, (float*)p_xC, nullptr,
                                      ROWS, 128, 512, 1024, 128, 128,
                                      512, (size_t)512 * 128, (size_t)8192 * 128);
    // sel softmax + row features
    k_rowprep<<<ROWS, 64>>>();

    // ---- operand conversion (hi planes only) ----
    k_cvtA<<<8192, 256>>>(x, (__half*)p_xA);
    k_convBt<<<dim3(96, 32, 1), 256>>>(W_sense, (__half*)p_WsT, 3072, 1024);

    // ---- senses = x @ W_sense + b_sense (1-term fp16) ----
    hgemm<1, 1, false, 0><<<dim3(24, 64, 1), 256, SM11>>>(
        (const __half*)p_xA, (const __half*)p_WsT, p_senses, b_sense,
        1024, 1024, 1024, 3072, 0, 0, 0, 0, 0, 0);

    // ---- combine (elementwise) -> xnew hi plane ----
    k_combine2<<<ROWS, 256>>>();

    // ---- scores + causal softmax -> fp16 attn ----
    k_scores<<<ROWS, 256>>>(w_charge, w_shell, w_distance, w_mass, w_valence, temperature);

    // ---- V = xnew @ W_v + b_v -> VT hi/lo planes (transposed epilogue) ----
    k_convBt<<<dim3(32, 32, 1), 256>>>(W_v, (__half*)p_WvT, 1024, 1024);
    hgemm<1, 1, false, 2><<<dim3(8, 64, 1), 256, SM11>>>(
        (const __half*)p_xnA, (const __half*)p_WvT, p_VT, b_v,
        1024, 1024, 1024, 0, 0, 0, PSVT, 0, 0, 0);

    // ---- attnout = attn @ V (causal, batched) -> aoA hi plane only ----
    hgemm<1, 2, true, 1><<<dim3(8, 16, 4), 256, SM12>>>(
        (const __half*)p_attnA, (const __half*)p_VT, p_aoA, nullptr,
        2048, 2048, 2048, 1024, 0, PSVT, 0,
        (size_t)2048 * 2048, (size_t)1024 * 2048, (size_t)2048 * 1024);

    // ---- out = attnout @ W_out + b_out (1-term) ----
    k_convBt<<<dim3(32, 32, 1), 256>>>(W_out, (__half*)p_WoT, 1024, 1024);
    hgemm<1, 1, false, 0><<<dim3(8, 64, 1), 256, SM11>>>(
        (const __half*)p_aoA, (const __half*)p_WoT, out, b_out,
        1024, 1024, 1024, 1024, 0, 0, 0, 0, 0, 0);

    (void)in_sizes; (void)n_in; (void)out_size;
}

// round 14
// speedup vs baseline: 1.0904x; 1.0904x over previous
#include <cuda_runtime.h>
#include <cuda_fp16.h>
#include <math.h>
#include <stdint.h>
#include <cstdint>

// Problem constants
#define BB 4
#define NN 2048
#define DD 1024
#define ROWS 8192      // B*N
#define NF 37
#define KXW 3104       // 3072 + 32 pad (bias rows at 3072..3074)

// ---------------- device scratch (allocation-free) ----------------
__device__ float g_partial[4 * 16 * 1024];
__device__ float g_xmean [4 * 1024];
__device__ float g_ctx   [4 * 1024];
__device__ float g_selctx[4 * 3];
__device__ float g_selw  [8192 * 3];
__device__ float g_rowf  [8192 * 8];
__device__ float g_compat[1024];
__device__ float g_Wfeat [1024 * NF];
__device__ float g_bfeat [NF];
__device__ float g_Wcomb [1024 * 128];   // cols 0..110 = Wsense@Wfeat, 111..113 = W_sel[:D]
__device__ float g_bcomb [3 * NF];
__device__ float g_xC    [2 * 8192 * 128];

// fp16 planes
__device__ __half g_xwA  [8192 * KXW];        // [w0*x | w1*x | w2*x | w0 w1 w2 0...]
__device__ __half g_WsT2 [1024 * KXW];        // stacked W_sense^T + bias rows
__device__ __half g_xnA  [8192 * 1024];       // xnew hi
__device__ __half g_WvT  [1024 * 1024];
__device__ __half g_VT   [4 * 1024 * 2048];   // hi only
__device__ __half g_attnA[8192 * 2048];
__device__ __half g_aoA  [8192 * 1024];
__device__ __half g_WoT  [1024 * 1024];

__device__ __forceinline__ float sp_(float z) {
    return z > 20.f ? z : log1pf(expf(z));
}
__device__ __forceinline__ float neg_inf_() { return __int_as_float(0xff800000u); }

__device__ __forceinline__ uint32_t smem_u32(const void* p) {
    uint32_t a;
    asm("{ .reg .u64 t; cvta.to.shared.u64 t, %1; cvt.u32.u64 %0, t; }" : "=r"(a) : "l"(p));
    return a;
}
__device__ __forceinline__ void ldm_x4(uint32_t* r, uint32_t addr) {
    asm volatile("ldmatrix.sync.aligned.m8n8.x4.shared.b16 {%0,%1,%2,%3}, [%4];"
        : "=r"(r[0]), "=r"(r[1]), "=r"(r[2]), "=r"(r[3]) : "r"(addr));
}
__device__ __forceinline__ void mma_f16(float* c, const uint32_t* a, const uint32_t* b) {
    asm volatile("mma.sync.aligned.m16n8k16.row.col.f32.f16.f16.f32 "
        "{%0,%1,%2,%3}, {%4,%5,%6,%7}, {%8,%9}, {%0,%1,%2,%3};"
        : "+f"(c[0]), "+f"(c[1]), "+f"(c[2]), "+f"(c[3])
        : "r"(a[0]), "r"(a[1]), "r"(a[2]), "r"(a[3]), "r"(b[0]), "r"(b[1]));
}
__device__ __forceinline__ void cp_async16(uint32_t s, const void* g) {
    asm volatile("cp.async.cg.shared.global [%0], [%1], 16;" :: "r"(s), "l"(g));
}
__device__ __forceinline__ void cp_commit() { asm volatile("cp.async.commit_group;" ::: "memory"); }
template<int N> __device__ __forceinline__ void cp_wait() {
    asm volatile("cp.async.wait_group %0;" :: "n"(N) : "memory");
}

// ---------------- fp16 split GEMM (mma.sync, 3-stage cp.async pipeline) ------
// C = A@B (+bias). A: SAP fp16 planes [M][K]; B: SBP planes [N][K].
// OUTM: 0 = fp32 row-major; 1 = fp16 hi plane (+lo iff psC); 2 = fp16 transposed
//       batch-split VT layout (hi; +lo iff psC).
template<int SAP, int SBP, bool CAUSAL, int OUTM>
__global__ __launch_bounds__(256, 2)
void hgemm(const __half* __restrict__ A, const __half* __restrict__ B,
           void* __restrict__ Cv, const float* __restrict__ bias,
           int K, int lda, int ldb, int ldc,
           size_t psA, size_t psB, size_t psC,
           size_t sA, size_t sB, size_t sC) {
    extern __shared__ char smx[];
    A += (size_t)blockIdx.z * sA;
    B += (size_t)blockIdx.z * sB;
    const int by = CAUSAL ? (gridDim.y - 1 - blockIdx.y) : blockIdx.y;
    const int rowStart = by * 128;
    const int colStart = blockIdx.x * 128;
    const int kmax = CAUSAL ? min(K, rowStart + 128) : K;
    const int tid = threadIdx.x, lane = tid & 31, wid = tid >> 5;
    const int mW = (wid >> 2) * 64, nW = (wid & 3) * 32;
    const uint32_t smBase = smem_u32(smx);
    constexpr uint32_t PL  = 8192u;
    constexpr uint32_t STG = (uint32_t)(SAP + SBP) * PL;
    constexpr int MAXS = (SAP > SBP) ? SAP : SBP;

    float acc[4][4][4];
    #pragma unroll
    for (int i = 0; i < 4; ++i)
        #pragma unroll
        for (int j = 0; j < 4; ++j)
            #pragma unroll
            for (int e = 0; e < 4; ++e) acc[i][j][e] = 0.f;

    const int rA = mW + (lane & 15);
    const int rB = nW + ((lane >> 4) << 3) + (lane & 7);
    const uint32_t swA = (uint32_t)((rA >> 1) & 3);
    const uint32_t swB = (uint32_t)((rB >> 1) & 3);
    const uint32_t cA = (uint32_t)(lane >> 4);
    const uint32_t cB = (uint32_t)((lane >> 3) & 1);
    uint32_t aRow[4], bRow[2];
    #pragma unroll
    for (int am = 0; am < 4; ++am) aRow[am] = (uint32_t)(rA + am * 16) * 64u;
    #pragma unroll
    for (int np = 0; np < 2; ++np) bRow[np] = (uint32_t)(rB + np * 16) * 64u;

    const int r2 = tid >> 2, c2 = tid & 3;

    auto loadStage = [&](int st, int k0) {
        uint32_t sb = smBase + (uint32_t)st * STG;
        #pragma unroll
        for (int p = 0; p < SAP; ++p) {
            const __half* gp = A + (size_t)p * psA + (size_t)rowStart * lda + k0;
            #pragma unroll
            for (int l = 0; l < 2; ++l) {
                int r = l * 64 + r2;
                uint32_t sa = sb + (uint32_t)p * PL + (uint32_t)r * 64u +
                              ((((uint32_t)c2) ^ (((uint32_t)r >> 1) & 3u)) << 4);
                cp_async16(sa, gp + (size_t)r * lda + c2 * 8);
            }
        }
        #pragma unroll
        for (int p = 0; p < SBP; ++p) {
            const __half* gp = B + (size_t)p * psB + (size_t)colStart * ldb + k0;
            #pragma unroll
            for (int l = 0; l < 2; ++l) {
                int r = l * 64 + r2;
                uint32_t sa = sb + (uint32_t)(SAP + p) * PL + (uint32_t)r * 64u +
                              ((((uint32_t)c2) ^ (((uint32_t)r >> 1) & 3u)) << 4);
                cp_async16(sa, gp + (size_t)r * ldb + c2 * 8);
            }
        }
    };

    const int nIter = kmax >> 5;
    if (0 < nIter) loadStage(0, 0);
    cp_commit();
    if (1 < nIter) loadStage(1, 32);
    cp_commit();

    for (int it = 0; it < nIter; ++it) {
        if (it + 1 < nIter) cp_wait<1>(); else cp_wait<0>();
        __syncthreads();
        int nl = it + 2;
        if (nl < nIter) loadStage(nl - (nl / 3) * 3, nl << 5);
        cp_commit();

        uint32_t sb = smBase + (uint32_t)(it - (it / 3) * 3) * STG;
        #pragma unroll
        for (int ks = 0; ks < 2; ++ks) {
            uint32_t af[SAP][4][4], bf[SBP][2][4];
            #pragma unroll
            for (int p = 0; p < SAP; ++p)
                #pragma unroll
                for (int am = 0; am < 4; ++am)
                    ldm_x4(af[p][am], sb + (uint32_t)p * PL + aRow[am] +
                           ((((uint32_t)(2 * ks) + cA) ^ swA) << 4));
            #pragma unroll
            for (int p = 0; p < SBP; ++p)
                #pragma unroll
                for (int np = 0; np < 2; ++np)
                    ldm_x4(bf[p][np], sb + (uint32_t)(SAP + p) * PL + bRow[np] +
                           ((((uint32_t)(2 * ks) + cB) ^ swB) << 4));
            #pragma unroll
            for (int ci = 0; ci < SAP; ++ci)
                #pragma unroll
                for (int cj = 0; cj < SBP; ++cj) {
                    if (ci + cj >= MAXS) continue;
                    #pragma unroll
                    for (int am = 0; am < 4; ++am)
                        #pragma unroll
                        for (int an = 0; an < 4; ++an)
                            mma_f16(acc[am][an], af[ci][am], &bf[cj][an >> 1][(an & 1) * 2]);
                }
        }
    }

    #pragma unroll
    for (int am = 0; am < 4; ++am) {
        int row = rowStart + mW + am * 16 + (lane >> 2);
        #pragma unroll
        for (int an = 0; an < 4; ++an) {
            int col = colStart + nW + an * 8 + (lane & 3) * 2;
            float b0 = bias ? bias[col] : 0.f, b1 = bias ? bias[col + 1] : 0.f;
            float v0 = acc[am][an][0] + b0, v1 = acc[am][an][1] + b1;
            float v2 = acc[am][an][2] + b0, v3 = acc[am][an][3] + b1;
            if (OUTM == 0) {
                float* C = (float*)Cv + (size_t)blockIdx.z * sC;
                *(float2*)(C + (size_t)row * ldc + col) = make_float2(v0, v1);
                *(float2*)(C + (size_t)(row + 8) * ldc + col) = make_float2(v2, v3);
            } else if (OUTM == 1) {
                __half* Cp = (__half*)Cv + (size_t)blockIdx.z * sC;
                __half h0 = __float2half(v0), h1 = __float2half(v1);
                __half h2 = __float2half(v2), h3 = __float2half(v3);
                __half2 hh01; hh01.x = h0; hh01.y = h1;
                __half2 hh23; hh23.x = h2; hh23.y = h3;
                *(__half2*)(Cp + (size_t)row * ldc + col) = hh01;
                *(__half2*)(Cp + (size_t)(row + 8) * ldc + col) = hh23;
                if (psC) {
                    __half2 ll01; ll01.x = __float2half(v0 - __half2float(h0));
                                  ll01.y = __float2half(v1 - __half2float(h1));
                    __half2 ll23; ll23.x = __float2half(v2 - __half2float(h2));
                                  ll23.y = __float2half(v3 - __half2float(h3));
                    *(__half2*)(Cp + psC + (size_t)row * ldc + col) = ll01;
                    *(__half2*)(Cp + psC + (size_t)(row + 8) * ldc + col) = ll23;
                }
            } else {
                // OUTM == 2: transposed batch-split VT write: VT[b][col][row&2047]
                __half* Cp = (__half*)Cv;
                size_t a0 = ((size_t)(row >> 11) << 21) + (size_t)col * 2048 + (row & 2047);
                __half h0 = __float2half(v0), h1 = __float2half(v1);
                __half h2 = __float2half(v2), h3 = __float2half(v3);
                Cp[a0]            = h0;
                Cp[a0 + 2048]     = h1;
                Cp[a0 + 8]        = h2;
                Cp[a0 + 2056]     = h3;
                if (psC) {
                    Cp[psC + a0]        = __float2half(v0 - __half2float(h0));
                    Cp[psC + a0 + 2048] = __float2half(v1 - __half2float(h1));
                    Cp[psC + a0 + 8]    = __float2half(v2 - __half2float(h2));
                    Cp[psC + a0 + 2056] = __float2half(v3 - __half2float(h3));
                }
            }
        }
    }
}

// ---------------- conversion / build kernels ----------------

// build xwA row: [w0*x | w1*x | w2*x | w0 w1 w2 0..0]
__global__ void k_buildxw(const float* __restrict__ x) {
    int row = blockIdx.x;          // 8192
    int tid = threadIdx.x;         // 256
    float w0 = g_selw[row * 3 + 0];
    float w1 = g_selw[row * 3 + 1];
    float w2 = g_selw[row * 3 + 2];
    const float4* xr = (const float4*)(x + (size_t)row * 1024);
    __half* dst = g_xwA + (size_t)row * KXW;
    float4 v = xr[tid];
    int o = tid * 4;
    __half2 a, b;
    a.x = __float2half(w0 * v.x); a.y = __float2half(w0 * v.y);
    b.x = __float2half(w0 * v.z); b.y = __float2half(w0 * v.w);
    *(__half2*)(dst + o) = a; *(__half2*)(dst + o + 2) = b;
    a.x = __float2half(w1 * v.x); a.y = __float2half(w1 * v.y);
    b.x = __float2half(w1 * v.z); b.y = __float2half(w1 * v.w);
    *(__half2*)(dst + 1024 + o) = a; *(__half2*)(dst + 1024 + o + 2) = b;
    a.x = __float2half(w2 * v.x); a.y = __float2half(w2 * v.y);
    b.x = __float2half(w2 * v.z); b.y = __float2half(w2 * v.w);
    *(__half2*)(dst + 2048 + o) = a; *(__half2*)(dst + 2048 + o + 2) = b;
    if (tid < 32) {
        float t = (tid == 0) ? w0 : (tid == 1) ? w1 : (tid == 2) ? w2 : 0.f;
        dst[3072 + tid] = __float2half(t);
    }
}

// build WsT2[n][k]: k<3072 -> W_sense[(k&1023)][ (k>>10)*1024 + n ]; 3072..3074 -> b_sense; else 0
__global__ void k_buildWsT2(const float* __restrict__ Ws, const float* __restrict__ bs) {
    int n0 = blockIdx.x * 32, k0 = blockIdx.y * 32;
    __shared__ float t[32][33];
    int tx = threadIdx.x & 31, ty = threadIdx.x >> 5;
    #pragma unroll
    for (int l = 0; l < 4; ++l) {
        int k = k0 + ty + l * 8;
        int n = n0 + tx;
        float v;
        if (k < 3072)      v = Ws[(size_t)(k & 1023) * 3072 + (k >> 10) * 1024 + n];
        else if (k < 3075) v = bs[(k - 3072) * 1024 + n];
        else               v = 0.f;
        t[ty + l * 8][tx] = v;
    }
    __syncthreads();
    #pragma unroll
    for (int l = 0; l < 4; ++l) {
        int n = ty + l * 8;
        g_WsT2[(size_t)(n0 + n) * KXW + k0 + tx] = __float2half(t[tx][n]);
    }
}

// transpose: dst[n][k] = fp16(src[k][n])
__global__ void k_convBt(const float* __restrict__ src, __half* __restrict__ dst,
                         int lds, int ldd) {
    int n0 = blockIdx.x * 32, k0 = blockIdx.y * 32;
    __shared__ float t[32][33];
    int tx = threadIdx.x & 31, ty = threadIdx.x >> 5;
    #pragma unroll
    for (int l = 0; l < 4; ++l)
        t[ty + l * 8][tx] = src[(size_t)(k0 + ty + l * 8) * lds + n0 + tx];
    __syncthreads();
    #pragma unroll
    for (int l = 0; l < 4; ++l) {
        int n = ty + l * 8;
        dst[(size_t)(n0 + n) * ldd + k0 + tx] = __float2half(t[tx][n]);
    }
}

// ---------------- merged prep kernels ----------------

// blocks [0,256): meanpart | 256: compat | [257,405): packfeat | [405,417): packsel
__global__ void k_prep1(const float* __restrict__ x, const float* __restrict__ L,
                        const float* __restrict__ W_charge, const float* __restrict__ b_charge,
                        const float* __restrict__ W_shell,  const float* __restrict__ b_shell,
                        const float* __restrict__ W_class,  const float* __restrict__ b_class,
                        const float* __restrict__ W_mass,   const float* __restrict__ b_mass,
                        const float* __restrict__ W_sel) {
    int blk = blockIdx.x, tid = threadIdx.x;
    if (blk < 256) {
        int d  = (blk & 3) * 256 + tid;
        int bc = blk >> 2;
        int b  = bc >> 4, c = bc & 15;
        const float* xp = x + ((size_t)b * NN + c * 128) * DD + d;
        float s = 0.f;
        #pragma unroll 8
        for (int n = 0; n < 128; n++) s += xp[(size_t)n * DD];
        g_partial[bc * 1024 + d] = s;
    } else if (blk == 256) {
        for (int t = tid; t < 1024; t += 256) {
            int i = t >> 5, j = t & 31;
            float v = (L[i * 32 + j] + L[j * 32 + i]) * 0.5f;
            g_compat[t] = 1.f / (1.f + expf(-v));
        }
    } else if (blk < 405) {
        int idx = (blk - 257) * 256 + tid;
        if (idx < 1024 * NF) {
            int k = idx / NF, c = idx % NF;
            float v;
            if (c == 0)       v = W_charge[k];
            else if (c <= 3)  v = W_shell[k * 3 + (c - 1)];
            else if (c <= 35) v = W_class[k * 32 + (c - 4)];
            else              v = W_mass[k];
            g_Wfeat[k * NF + c] = v;
        }
        if (idx < NF) {
            float v;
            if (idx == 0)       v = b_charge[0];
            else if (idx <= 3)  v = b_shell[idx - 1];
            else if (idx <= 35) v = b_class[idx - 4];
            else                v = b_mass[0];
            g_bfeat[idx] = v;
        }
    } else {
        int idx = (blk - 405) * 256 + tid;    // 0..3071
        if (idx < 3072) {
            int k = idx / 3, s = idx % 3;
            g_Wcomb[k * 128 + 111 + s] = W_sel[(size_t)k * 3 + s];
        }
    }
}

// blocks [0,16): meanfin | 16: bcomb
__global__ void k_prep2(const float* __restrict__ b_sense) {
    int blk = blockIdx.x, tid = threadIdx.x;
    if (blk < 16) {
        int idx = blk * 256 + tid;
        int b = idx >> 10, d = idx & 1023;
        float s = 0.f;
        #pragma unroll
        for (int c = 0; c < 16; c++) s += g_partial[(b * 16 + c) * 1024 + d];
        g_xmean[idx] = s * (1.f / (float)NN);
    } else {
        int c = tid;
        if (c < 3 * NF) {
            int s = c / NF, cc = c % NF;
            float acc = 0.f;
            for (int k = 0; k < 1024; k++)
                acc += b_sense[s * 1024 + k] * g_Wfeat[k * NF + cc];
            g_bcomb[c] = acc;
        }
    }
}

__global__ void k_ctxpart(const float* __restrict__ W_ctx) {
    int d = blockIdx.x * 256 + threadIdx.x;
    int b = blockIdx.y;
    int z = blockIdx.z;
    const float* xm = g_xmean + b * 1024 + z * 128;
    const float* W  = W_ctx + (size_t)(z * 128) * 1024 + d;
    float acc = 0.f;
    #pragma unroll 8
    for (int k = 0; k < 128; k++) acc += xm[k] * W[(size_t)k * 1024];
    g_partial[(z * 4 + b) * 1024 + d] = acc;
}

__global__ void k_ctxfin(const float* __restrict__ b_ctx) {
    int idx = blockIdx.x * 256 + threadIdx.x;
    int b = idx >> 10, d = idx & 1023;
    float s = 0.f;
    #pragma unroll
    for (int z = 0; z < 8; z++) s += g_partial[(z * 4 + b) * 1024 + d];
    g_ctx[idx] = s + b_ctx[d];
}

__global__ void k_selctx(const float* __restrict__ W_sel, const float* __restrict__ b_sel) {
    int s = blockIdx.x, b = blockIdx.y;
    int tid = threadIdx.x;
    const float* c = g_ctx + b * 1024;
    float p = 0.f;
    for (int k = tid; k < 1024; k += 128) p += c[k] * W_sel[(size_t)(1024 + k) * 3 + s];
    __shared__ float red[128];
    red[tid] = p; __syncthreads();
    for (int o = 64; o; o >>= 1) { if (tid < o) red[tid] += red[tid + o]; __syncthreads(); }
    if (tid == 0) g_selctx[b * 3 + s] = red[0] + b_sel[s];
}

// per-row: sel softmax (from xC cols 111..113) -> g_selw, then features -> g_rowf
__global__ void k_rowprep() {
    int row = blockIdx.x;
    int b   = row >> 11;
    int tid = threadIdx.x;   // 64
    __shared__ float fv[NF];
    __shared__ float sw[3];
    const float* xc0 = g_xC + (size_t)row * 128;
    const float* xc1 = g_xC + (size_t)8192 * 128 + (size_t)row * 128;
    if (tid < 3)
        fv[tid] = xc0[111 + tid] + xc1[111 + tid] + g_selctx[b * 3 + tid];
    __syncthreads();
    if (tid == 0) {
        float l0 = fv[0], l1 = fv[1], l2 = fv[2];
        float m = fmaxf(l0, fmaxf(l1, l2));
        float e0 = expf(l0 - m), e1 = expf(l1 - m), e2 = expf(l2 - m);
        float inv = 1.f / (e0 + e1 + e2);
        sw[0] = e0 * inv; sw[1] = e1 * inv; sw[2] = e2 * inv;
        g_selw[row * 3 + 0] = sw[0];
        g_selw[row * 3 + 1] = sw[1];
        g_selw[row * 3 + 2] = sw[2];
    }
    __syncthreads();
    if (tid < NF) {
        float v0 = xc0[tid]          + xc1[tid]          + g_bcomb[tid];
        float v1 = xc0[NF + tid]     + xc1[NF + tid]     + g_bcomb[NF + tid];
        float v2 = xc0[2 * NF + tid] + xc1[2 * NF + tid] + g_bcomb[2 * NF + tid];
        fv[tid] = g_bfeat[tid] + sw[0] * v0 + sw[1] * v1 + sw[2] * v2;
    }
    __syncthreads();
    if (tid == 0) {
        float* rf = g_rowf + (size_t)row * 8;
        rf[0] = tanhf(fv[0]);
        float s0 = fv[1], s1 = fv[2], s2 = fv[3];
        float m = fmaxf(s0, fmaxf(s1, s2));
        float e0 = expf(s0 - m), e1 = expf(s1 - m), e2 = expf(s2 - m);
        float inv = 1.f / (e0 + e1 + e2);
        rf[1] = e0 * inv; rf[2] = e1 * inv; rf[3] = e2 * inv;
        float best = fv[4]; int bi = 0;
        #pragma unroll
        for (int c = 1; c < 32; c++) { float v = fv[4 + c]; if (v > best) { best = v; bi = c; } }
        rf[4] = sp_(fv[36]) + 0.5f;
        rf[5] = __int_as_float(bi);
        rf[6] = 0.f; rf[7] = 0.f;
    }
}

// energy scores + causal softmax (bounded loops) -> fp16 attn plane
__global__ void k_scores(const float* __restrict__ w_charge, const float* __restrict__ w_shell,
                         const float* __restrict__ w_distance, const float* __restrict__ w_mass,
                         const float* __restrict__ w_valence, const float* __restrict__ temperature) {
    int gi = blockIdx.x;
    int b  = gi >> 11;
    int i  = NN - 1 - (gi & 2047);
    int rowEnd = ((i >> 7) + 1) << 7;
    int tid = threadIdx.x;
    __shared__ float sc[2048];
    __shared__ float cp[1024];
    __shared__ float red[256];
    for (int t = tid; t < 1024; t += 256) cp[t] = g_compat[t];

    float spc = sp_(w_charge[0]);
    float sps = sp_(w_shell[0]);
    float spd = sp_(w_distance[0]);
    float spm = sp_(w_mass[0]);
    float spv = sp_(w_valence[0]);
    float invt = 1.f / sp_(temperature[0]);

    const float4* rf = (const float4*)g_rowf;
    int base = b * NN;
    float4 m0 = rf[(size_t)(base + i) * 2];
    float4 m1 = rf[(size_t)(base + i) * 2 + 1];
    float ci = m0.x, si0 = m0.y, si1 = m0.z, si2 = m0.w;
    float mi = m1.x;
    int cli = __float_as_int(m1.y) * 32;
    __syncthreads();

    for (int j = tid; j <= i; j += 256) {
        float4 f0 = rf[(size_t)(base + j) * 2];
        float4 f1 = rf[(size_t)(base + j) * 2 + 1];
        float d0 = fabsf(si0 - f0.y);
        float d1 = fabsf(si1 - f0.z);
        float d2 = fabsf(si2 - f0.w);
        float dist = (float)(i - j);
        float E = spc * ci * f0.x + sps * (d0 + d1 + d2)
                - spd * __fdividef(1.f, 1.f + 0.1f * dist)
                + spm * 0.1f * mi * f1.x - spv;
        sc[j] = -E * invt * cp[cli + __float_as_int(f1.y)];
    }
    __syncthreads();

    float lm = neg_inf_();
    for (int j = tid; j <= i; j += 256) lm = fmaxf(lm, sc[j]);
    red[tid] = lm; __syncthreads();
    for (int o = 128; o; o >>= 1) { if (tid < o) red[tid] = fmaxf(red[tid], red[tid + o]); __syncthreads(); }
    float mx = red[0]; __syncthreads();

    float ls = 0.f;
    for (int j = tid; j <= i; j += 256) { float e = expf(sc[j] - mx); sc[j] = e; ls += e; }
    red[tid] = ls; __syncthreads();
    for (int o = 128; o; o >>= 1) { if (tid < o) red[tid] += red[tid + o]; __syncthreads(); }
    float inv = 1.f / red[0];

    __half* ar = g_attnA + (size_t)(base + i) * NN;
    for (int j = tid; j < rowEnd; j += 256)
        ar[j] = __float2half(j <= i ? sc[j] * inv : 0.f);
}

// ---------------- fp32 tiled SGEMM (feat path, with batch strides) -----------
__global__ __launch_bounds__(256)
void sgemm128(const float* __restrict__ A, const float* __restrict__ B,
              float* __restrict__ C, const float* __restrict__ bias,
              int M, int N, int K, int lda, int ldb, int ldc,
              size_t sA, size_t sB, size_t sC) {
    A += (size_t)blockIdx.z * sA;
    B += (size_t)blockIdx.z * sB;
    C += (size_t)blockIdx.z * sC;
    int rowStart = blockIdx.y * 128;
    int colStart = blockIdx.x * 128;

    __shared__ float As[16][128];
    __shared__ float Bs[16][128];
    int tid = threadIdx.x;
    int tx = tid & 15, ty = tid >> 4;
    float acc[8][8];
    #pragma unroll
    for (int i = 0; i < 8; i++)
        #pragma unroll
        for (int j = 0; j < 8; j++) acc[i][j] = 0.f;

    const bool n_vec = ((N & 3) == 0);

    for (int k0 = 0; k0 < K; k0 += 16) {
        #pragma unroll
        for (int l = 0; l < 2; l++) {
            int idx = tid + l * 256;
            int m = idx >> 2;
            int kq = (idx & 3) * 4;
            float4 v = *reinterpret_cast<const float4*>(
                A + (size_t)(rowStart + m) * lda + k0 + kq);
            As[kq + 0][m] = v.x; As[kq + 1][m] = v.y; As[kq + 2][m] = v.z; As[kq + 3][m] = v.w;
        }
        #pragma unroll
        for (int l = 0; l < 2; l++) {
            int idx = tid + l * 256;
            int kr = idx >> 5;
            int nq = (idx & 31) * 4;
            int col = colStart + nq;
            float4 v;
            if (n_vec && col + 3 < N) {
                v = *reinterpret_cast<const float4*>(B + (size_t)(k0 + kr) * ldb + col);
            } else {
                const float* bp = B + (size_t)(k0 + kr) * ldb;
                v.x = (col + 0 < N) ? bp[col + 0] : 0.f;
                v.y = (col + 1 < N) ? bp[col + 1] : 0.f;
                v.z = (col + 2 < N) ? bp[col + 2] : 0.f;
                v.w = (col + 3 < N) ? bp[col + 3] : 0.f;
            }
            *reinterpret_cast<float4*>(&Bs[kr][nq]) = v;
        }
        __syncthreads();
        #pragma unroll
        for (int kk = 0; kk < 16; kk++) {
            float ra[8], rb[8];
            *(float4*)&ra[0] = *(float4*)&As[kk][ty * 8];
            *(float4*)&ra[4] = *(float4*)&As[kk][ty * 8 + 4];
            *(float4*)&rb[0] = *(float4*)&Bs[kk][tx * 8];
            *(float4*)&rb[4] = *(float4*)&Bs[kk][tx * 8 + 4];
            #pragma unroll
            for (int i = 0; i < 8; i++)
                #pragma unroll
                for (int j = 0; j < 8; j++)
                    acc[i][j] += ra[i] * rb[j];
        }
        __syncthreads();
    }

    #pragma unroll
    for (int i = 0; i < 8; i++) {
        size_t row = rowStart + ty * 8 + i;
        #pragma unroll
        for (int j = 0; j < 8; j++) {
            int col = colStart + tx * 8 + j;
            if (col < N) {
                float v = acc[i][j] + (bias ? bias[col] : 0.f);
                C[row * (size_t)ldc + col] = v;
            }
        }
    }
}

// ---------------- host ----------------
extern "C" void kernel_launch(void* const* d_in, const int* in_sizes, int n_in,
                              void* d_out, int out_size) {
    const float* x         = (const float*)d_in[0];
    const float* W_sense   = (const float*)d_in[1];
    const float* b_sense   = (const float*)d_in[2];
    const float* W_ctx     = (const float*)d_in[3];
    const float* b_ctx     = (const float*)d_in[4];
    const float* W_sel     = (const float*)d_in[5];
    const float* b_sel     = (const float*)d_in[6];
    const float* W_charge  = (const float*)d_in[7];
    const float* b_charge  = (const float*)d_in[8];
    const float* W_shell   = (const float*)d_in[9];
    const float* b_shell   = (const float*)d_in[10];
    const float* W_class   = (const float*)d_in[11];
    const float* b_class   = (const float*)d_in[12];
    const float* W_mass    = (const float*)d_in[13];
    const float* b_mass    = (const float*)d_in[14];
    const float* compatL   = (const float*)d_in[17];
    const float* w_charge  = (const float*)d_in[18];
    const float* w_shell   = (const float*)d_in[19];
    const float* w_distance= (const float*)d_in[20];
    const float* w_mass    = (const float*)d_in[21];
    const float* w_valence = (const float*)d_in[22];
    const float* temperature=(const float*)d_in[23];
    const float* W_v       = (const float*)d_in[24];
    const float* b_v       = (const float*)d_in[25];
    const float* W_out     = (const float*)d_in[26];
    const float* b_out     = (const float*)d_in[27];
    float* out = (float*)d_out;

    void *p_Wfeat, *p_Wcomb, *p_xC;
    void *p_xwA, *p_WsT2, *p_xnA, *p_WvT, *p_VT, *p_attnA, *p_aoA, *p_WoT;
    cudaGetSymbolAddress(&p_Wfeat,  g_Wfeat);
    cudaGetSymbolAddress(&p_Wcomb,  g_Wcomb);
    cudaGetSymbolAddress(&p_xC,     g_xC);
    cudaGetSymbolAddress(&p_xwA,    g_xwA);
    cudaGetSymbolAddress(&p_WsT2,   g_WsT2);
    cudaGetSymbolAddress(&p_xnA,    g_xnA);
    cudaGetSymbolAddress(&p_WvT,    g_WvT);
    cudaGetSymbolAddress(&p_VT,     g_VT);
    cudaGetSymbolAddress(&p_attnA,  g_attnA);
    cudaGetSymbolAddress(&p_aoA,    g_aoA);
    cudaGetSymbolAddress(&p_WoT,    g_WoT);

    const int SM11 = 3 * 2 * 8192;   // 49152
    cudaFuncSetAttribute(hgemm<1, 1, false, 0>, cudaFuncAttributeMaxDynamicSharedMemorySize, SM11);
    cudaFuncSetAttribute(hgemm<1, 1, false, 1>, cudaFuncAttributeMaxDynamicSharedMemorySize, SM11);
    cudaFuncSetAttribute(hgemm<1, 1, false, 2>, cudaFuncAttributeMaxDynamicSharedMemorySize, SM11);
    cudaFuncSetAttribute(hgemm<1, 1, true, 1>,  cudaFuncAttributeMaxDynamicSharedMemorySize, SM11);

    // ---- prep (merged) ----
    k_prep1<<<417, 256>>>(x, compatL, W_charge, b_charge, W_shell, b_shell,
                          W_class, b_class, W_mass, b_mass, W_sel);
    k_prep2<<<17, 256>>>(b_sense);
    k_ctxpart<<<dim3(4, 4, 8), 256>>>(W_ctx);
    k_ctxfin<<<16, 256>>>(b_ctx);
    k_selctx<<<dim3(3, 4), 128>>>(W_sel, b_sel);
    // Wcomb cols 0..110
    sgemm128<<<dim3(1, 8, 3), 256>>>(W_sense, (const float*)p_Wfeat, (float*)p_Wcomb, nullptr,
                                     1024, NF, 1024, 3072, NF, 128,
                                     1024, 0, NF);
    // xC = x @ Wcomb (feat partials + sel logits), split-K 2
    sgemm128<<<dim3(1, 64, 2), 256>>>(x, (const float*)p_Wcomb, (float*)p_xC, nullptr,
                                      ROWS, 128, 512, 1024, 128, 128,
                                      512, (size_t)512 * 128, (size_t)8192 * 128);
    // sel softmax + row features
    k_rowprep<<<ROWS, 64>>>();

    // ---- build fused senses operands ----
    k_buildWsT2<<<dim3(32, 97), 256>>>(W_sense, b_sense);
    k_buildxw<<<ROWS, 256>>>(x);

    // ---- xnew = [w*x] @ [stacked Ws] (bias folded in K) -> xnA fp16 ----
    hgemm<1, 1, false, 1><<<dim3(8, 64, 1), 256, SM11>>>(
        (const __half*)p_xwA, (const __half*)p_WsT2, p_xnA, nullptr,
        KXW, KXW, KXW, 1024, 0, 0, 0, 0, 0, 0);

    // ---- scores + causal softmax -> fp16 attn ----
    k_scores<<<ROWS, 256>>>(w_charge, w_shell, w_distance, w_mass, w_valence, temperature);

    // ---- V = xnew @ W_v + b_v -> VT hi plane (transposed epilogue) ----
    k_convBt<<<dim3(32, 32, 1), 256>>>(W_v, (__half*)p_WvT, 1024, 1024);
    hgemm<1, 1, false, 2><<<dim3(8, 64, 1), 256, SM11>>>(
        (const __half*)p_xnA, (const __half*)p_WvT, p_VT, b_v,
        1024, 1024, 1024, 0, 0, 0, 0, 0, 0, 0);

    // ---- attnout = attn @ V (causal, batched, 1-term) -> aoA hi ----
    hgemm<1, 1, true, 1><<<dim3(8, 16, 4), 256, SM11>>>(
        (const __half*)p_attnA, (const __half*)p_VT, p_aoA, nullptr,
        2048, 2048, 2048, 1024, 0, 0, 0,
        (size_t)2048 * 2048, (size_t)1024 * 2048, (size_t)2048 * 1024);

    // ---- out = attnout @ W_out + b_out (1-term) ----
    k_convBt<<<dim3(32, 32, 1), 256>>>(W_out, (__half*)p_WoT, 1024, 1024);
    hgemm<1, 1, false, 0><<<dim3(8, 64, 1), 256, SM11>>>(
        (const __half*)p_aoA, (const __half*)p_WoT, out, b_out,
        1024, 1024, 1024, 1024, 0, 0, 0, 0, 0, 0);

    (void)in_sizes; (void)n_in; (void)out_size;
}